// round 3
// baseline (speedup 1.0000x reference)
#include <cuda_runtime.h>

// GCN_61701500174370: 2-layer GCN, N=100000 nodes, E=3200000 edges,
// features 128 -> 32 -> 16 -> 1, PyG gcn_norm with self-loops.
//
// Inputs (metadata order):
//  0: x        float32 [N,128]
//  1: edge_idx int32   [2,E]   (JAX x64 disabled => int32!)  row=ei[0:E], col=ei[E:2E]
//  2: edge_w   float32 [E]
//  3: W1 [128,32]  4: b1 [32]  5: W2 [32,16]  6: b2 [16]  7: Wfc [16,1]  8: bfc [1]
// Output: float32 [N,1]

#define GCN_N 100000
#define GCN_E 3200000
#define F1 32
#define F2 16

// ---------------- scratch (static device globals; pointers fetched host-side
// via cudaGetSymbolAddress and passed as kernel params) ----------------------
__device__ float g_deg [GCN_N];
__device__ float g_dinv[GCN_N];
__device__ float g_h1  [GCN_N * F1];
__device__ float g_agg1[GCN_N * F1];
__device__ float g_h2  [GCN_N * F2];
__device__ float g_agg2[GCN_N * F2];

static __device__ __forceinline__ float lrelu(float v) {
    return v > 0.0f ? v : 0.01f * v;
}

// ---------------- degree / normalization ----------------------------------
__global__ void k_deg_init(float* __restrict__ deg, int n) {
    int i = blockIdx.x * blockDim.x + threadIdx.x;
    if (i < n) deg[i] = 1.0f;   // self-loop weight 1
}

__global__ void k_deg_accum(const int* __restrict__ ei,
                            const float* __restrict__ w,
                            float* __restrict__ deg, int e_cnt, int n) {
    int e = blockIdx.x * blockDim.x + threadIdx.x;
    if (e < e_cnt) {
        int c = ei[e_cnt + e];   // col (target)
        if ((unsigned)c < (unsigned)n) atomicAdd(deg + c, w[e]);
    }
}

__global__ void k_dinv(const float* __restrict__ deg,
                       float* __restrict__ dinv, int n) {
    int i = blockIdx.x * blockDim.x + threadIdx.x;
    if (i < n) dinv[i] = rsqrtf(deg[i]);  // deg >= 1 always (self-loop)
}

// ---------------- layer-1 transform: h1 = x @ W1 ---------------------------
// 256 threads = 8 warps, one node row per warp; W1 staged in shared.
__global__ void k_gemm1(const float* __restrict__ x,
                        const float* __restrict__ W1,
                        float* __restrict__ h1, int n) {
    __shared__ float Ws[128 * F1];     // 16 KB
    __shared__ float xs[8][128];       //  4 KB
    int tid = threadIdx.x;
    for (int i = tid; i < 128 * F1; i += 256) Ws[i] = W1[i];
    __syncthreads();

    int warp = tid >> 5, lane = tid & 31;
    int row = blockIdx.x * 8 + warp;
    if (row < n) {
        const float* xr = x + (size_t)row * 128;
#pragma unroll
        for (int q = 0; q < 4; q++)
            xs[warp][lane + 32 * q] = xr[lane + 32 * q];
        __syncwarp();
        float acc = 0.0f;
#pragma unroll
        for (int k = 0; k < 128; k++) acc += xs[warp][k] * Ws[k * F1 + lane];
        h1[(size_t)row * F1 + lane] = acc;
    }
}

// ---------------- self-loop contribution (initializes agg buffers) --------
__global__ void k_selfloop1(const float* __restrict__ h1,
                            const float* __restrict__ dinv,
                            float* __restrict__ agg1, int n) {
    int idx = blockIdx.x * blockDim.x + threadIdx.x;
    if (idx < n * F1) {
        int i = idx >> 5;  // / F1
        float d = dinv[i];
        agg1[idx] = h1[idx] * d * d;
    }
}

__global__ void k_selfloop2(const float* __restrict__ h2,
                            const float* __restrict__ dinv,
                            float* __restrict__ agg2, int n) {
    int idx = blockIdx.x * blockDim.x + threadIdx.x;
    if (idx < n * F2) {
        int i = idx >> 4;  // / F2
        float d = dinv[i];
        agg2[idx] = h2[idx] * d * d;
    }
}

// ---------------- edge scatter, layer 1: one warp per edge -----------------
// Lanes 0..31 carry the 32 features; edge scalars come in as warp-broadcast
// global loads (single transaction each).
__global__ void k_scatter1(const int* __restrict__ ei,
                           const float* __restrict__ w,
                           const float* __restrict__ dinv,
                           const float* __restrict__ h1,
                           float* __restrict__ agg1, int e_cnt, int n) {
    int gw   = (blockIdx.x * blockDim.x + threadIdx.x) >> 5;  // global warp id
    int lane = threadIdx.x & 31;
    if (gw < e_cnt) {
        int r = ei[gw];
        int c = ei[e_cnt + gw];
        if ((unsigned)r < (unsigned)n && (unsigned)c < (unsigned)n) {
            float cw = dinv[r] * w[gw] * dinv[c];
            atomicAdd(agg1 + (size_t)c * F1 + lane,
                      h1[(size_t)r * F1 + lane] * cw);
        }
    }
}

// ---------------- layer-2 transform (fused bias + leakyReLU on input) ------
// h2 = lrelu(agg1 + b1) @ W2 ; one row per warp, shfl-broadcast reduction.
__global__ void k_gemm2(const float* __restrict__ agg1,
                        const float* __restrict__ b1,
                        const float* __restrict__ W2,
                        float* __restrict__ h2, int n) {
    __shared__ float Ws[F1 * F2];   // 512 floats
    __shared__ float bs[F1];
    int tid = threadIdx.x;
    for (int i = tid; i < F1 * F2; i += 256) Ws[i] = W2[i];
    if (tid < F1) bs[tid] = b1[tid];
    __syncthreads();

    int warp = tid >> 5, lane = tid & 31;
    int row = blockIdx.x * 8 + warp;
    if (row < n) {
        float v = lrelu(agg1[(size_t)row * F1 + lane] + bs[lane]);
        float acc = 0.0f;
#pragma unroll
        for (int k = 0; k < F1; k++) {
            float hk = __shfl_sync(0xffffffffu, v, k);
            acc += hk * Ws[k * F2 + (lane & 15)];
        }
        if (lane < F2) h2[(size_t)row * F2 + lane] = acc;
    }
}

// ---------------- edge scatter, layer 2: two edges per warp ----------------
__global__ void k_scatter2(const int* __restrict__ ei,
                           const float* __restrict__ w,
                           const float* __restrict__ dinv,
                           const float* __restrict__ h2,
                           float* __restrict__ agg2, int e_cnt, int n) {
    int gw   = (blockIdx.x * blockDim.x + threadIdx.x) >> 5;  // warp id
    int lane = threadIdx.x & 31;
    int f    = lane & 15;
    int e    = gw * 2 + (lane >> 4);
    if (e < e_cnt) {
        int r = ei[e];
        int c = ei[e_cnt + e];
        if ((unsigned)r < (unsigned)n && (unsigned)c < (unsigned)n) {
            float cw = dinv[r] * w[e] * dinv[c];
            atomicAdd(agg2 + (size_t)c * F2 + f,
                      h2[(size_t)r * F2 + f] * cw);
        }
    }
}

// ---------------- final: out = lrelu(agg2 + b2) @ Wfc + bfc ----------------
__global__ void k_final(const float* __restrict__ agg2,
                        const float* __restrict__ b2,
                        const float* __restrict__ Wfc,
                        const float* __restrict__ bfc,
                        float* __restrict__ out, int n) {
    int i = blockIdx.x * blockDim.x + threadIdx.x;
    if (i < n) {
        float acc = 0.0f;
#pragma unroll
        for (int t = 0; t < F2; t++) {
            acc += lrelu(agg2[(size_t)i * F2 + t] + b2[t]) * Wfc[t];
        }
        out[i] = acc + bfc[0];
    }
}

// ---------------- launcher --------------------------------------------------
extern "C" void kernel_launch(void* const* d_in, const int* in_sizes, int n_in,
                              void* d_out, int out_size) {
    const float* x   = (const float*)d_in[0];
    const int*   ei  = (const int*)d_in[1];     // int32 (JAX default x64 off)
    const float* w   = (const float*)d_in[2];
    const float* W1  = (const float*)d_in[3];
    const float* b1  = (const float*)d_in[4];
    const float* W2  = (const float*)d_in[5];
    const float* b2  = (const float*)d_in[6];
    const float* Wfc = (const float*)d_in[7];
    const float* bfc = (const float*)d_in[8];
    float*       out = (float*)d_out;

    int n = in_sizes[0] / 128;   // 100000
    int e = in_sizes[2];         // 3200000

    // Scratch pointers via symbol query (no allocation; capture-safe).
    float *deg, *dinv, *h1, *agg1, *h2, *agg2;
    cudaGetSymbolAddress((void**)&deg,  g_deg);
    cudaGetSymbolAddress((void**)&dinv, g_dinv);
    cudaGetSymbolAddress((void**)&h1,   g_h1);
    cudaGetSymbolAddress((void**)&agg1, g_agg1);
    cudaGetSymbolAddress((void**)&h2,   g_h2);
    cudaGetSymbolAddress((void**)&agg2, g_agg2);

    // normalization
    k_deg_init <<<(n + 255) / 256, 256>>>(deg, n);
    k_deg_accum<<<(e + 255) / 256, 256>>>(ei, w, deg, e, n);
    k_dinv     <<<(n + 255) / 256, 256>>>(deg, dinv, n);

    // layer 1
    k_gemm1    <<<(n + 7) / 8, 256>>>(x, W1, h1, n);
    k_selfloop1<<<(n * F1 + 255) / 256, 256>>>(h1, dinv, agg1, n);
    {
        long long threads = (long long)e * 32;
        k_scatter1<<<(unsigned)((threads + 255) / 256), 256>>>(ei, w, dinv, h1, agg1, e, n);
    }

    // layer 2 (bias+lrelu of layer 1 fused into transform)
    k_gemm2    <<<(n + 7) / 8, 256>>>(agg1, b1, W2, h2, n);
    k_selfloop2<<<(n * F2 + 255) / 256, 256>>>(h2, dinv, agg2, n);
    {
        long long threads = (long long)e * 16;
        k_scatter2<<<(unsigned)((threads + 255) / 256), 256>>>(ei, w, dinv, h2, agg2, e, n);
    }

    // output head
    k_final    <<<(n + 255) / 256, 256>>>(agg2, b2, Wfc, bfc, out, n);
}

// round 4
// speedup vs baseline: 2.2303x; 2.2303x over previous
#include <cuda_runtime.h>

// GCN_61701500174370: 2-layer GCN, N=100000 nodes, E=3200000 edges,
// features 128 -> 32 -> 16 -> 1, PyG gcn_norm with self-loops.
//
// Strategy: build CSR by target node once per call, precompute normalized
// edge weights, then do deterministic warp-per-node gather reductions
// (no float atomics). Layer-1 aggregation is fused with the layer-2
// transform; layer-2 aggregation is fused with the output head.
//
// Inputs (metadata order):
//  0: x        float32 [N,128]
//  1: edge_idx int32   [2,E]   row=ei[0:E], col=ei[E:2E]
//  2: edge_w   float32 [E]
//  3: W1 [128,32]  4: b1 [32]  5: W2 [32,16]  6: b2 [16]  7: Wfc [16,1]  8: bfc [1]
// Output: float32 [N,1]

#define GCN_N 100000
#define GCN_E 3200000
#define F1 32
#define F2 16
#define SCAN_BLK 1024

// ---------------- scratch (device globals; pointers fetched host-side) -----
__device__ float g_deg   [GCN_N];
__device__ float g_dinv  [GCN_N];
__device__ int   g_cnt   [GCN_N];
__device__ int   g_rowptr[GCN_N];
__device__ int   g_cursor[GCN_N];
__device__ int   g_bsum  [128];
__device__ int   g_src   [GCN_E];
__device__ float g_wn    [GCN_E];
__device__ float g_h1    [GCN_N * F1];
__device__ float g_h2    [GCN_N * F2];

static __device__ __forceinline__ float lrelu(float v) {
    return v > 0.0f ? v : 0.01f * v;
}

// ---------------- init: deg=1 (self-loop), cnt=0 ---------------------------
__global__ void k_init(float* __restrict__ deg, int* __restrict__ cnt, int n) {
    int i = blockIdx.x * blockDim.x + threadIdx.x;
    if (i < n) { deg[i] = 1.0f; cnt[i] = 0; }
}

// ---------------- weighted degree + edge count histogram -------------------
__global__ void k_count(const int* __restrict__ ei, const float* __restrict__ w,
                        float* __restrict__ deg, int* __restrict__ cnt,
                        int e_cnt, int n) {
    int e = blockIdx.x * blockDim.x + threadIdx.x;
    if (e < e_cnt) {
        int c = ei[e_cnt + e];
        if ((unsigned)c < (unsigned)n) {
            atomicAdd(deg + c, w[e]);
            atomicAdd(cnt + c, 1);
        }
    }
}

__global__ void k_dinv(const float* __restrict__ deg,
                       float* __restrict__ dinv, int n) {
    int i = blockIdx.x * blockDim.x + threadIdx.x;
    if (i < n) dinv[i] = rsqrtf(deg[i]);
}

// ---------------- exclusive scan of cnt -> rowptr (3 phases) ---------------
__global__ void k_scan1(const int* __restrict__ cnt, int* __restrict__ rowptr,
                        int* __restrict__ bsum, int n) {
    __shared__ int s[SCAN_BLK];
    int tid = threadIdx.x;
    int i = blockIdx.x * SCAN_BLK + tid;
    int own = (i < n) ? cnt[i] : 0;
    s[tid] = own;
    __syncthreads();
#pragma unroll
    for (int off = 1; off < SCAN_BLK; off <<= 1) {
        int t = (tid >= off) ? s[tid - off] : 0;
        __syncthreads();
        s[tid] += t;
        __syncthreads();
    }
    if (i < n) rowptr[i] = s[tid] - own;          // exclusive
    if (tid == SCAN_BLK - 1) bsum[blockIdx.x] = s[tid];  // block total
}

__global__ void k_scan2(int* __restrict__ bsum, int nb) {
    __shared__ int s[128];
    int tid = threadIdx.x;
    int own = (tid < nb) ? bsum[tid] : 0;
    s[tid] = own;
    __syncthreads();
#pragma unroll
    for (int off = 1; off < 128; off <<= 1) {
        int t = (tid >= off) ? s[tid - off] : 0;
        __syncthreads();
        s[tid] += t;
        __syncthreads();
    }
    if (tid < nb) bsum[tid] = s[tid] - own;       // exclusive block offsets
}

__global__ void k_scan3(int* __restrict__ rowptr, int* __restrict__ cursor,
                        const int* __restrict__ bsum, int n) {
    int i = blockIdx.x * blockDim.x + threadIdx.x;
    if (i < n) {
        int v = rowptr[i] + bsum[i / SCAN_BLK];
        rowptr[i] = v;
        cursor[i] = v;
    }
}

// ---------------- CSR fill with precomputed normalized weight --------------
__global__ void k_fill(const int* __restrict__ ei, const float* __restrict__ w,
                       const float* __restrict__ dinv,
                       int* __restrict__ cursor,
                       int* __restrict__ src, float* __restrict__ wn,
                       int e_cnt, int n) {
    int e = blockIdx.x * blockDim.x + threadIdx.x;
    if (e < e_cnt) {
        int r = ei[e];
        int c = ei[e_cnt + e];
        if ((unsigned)r < (unsigned)n && (unsigned)c < (unsigned)n) {
            int pos = atomicAdd(cursor + c, 1);
            src[pos] = r;
            wn[pos]  = dinv[r] * w[e] * dinv[c];
        }
    }
}

// ---------------- layer-1 transform: h1 = x @ W1 ---------------------------
// 8 warps/block, 4 rows/warp: Ws LDS amortized 4x; x in registers via shfl.
__global__ void k_gemm1(const float* __restrict__ x,
                        const float* __restrict__ W1,
                        float* __restrict__ h1, int n) {
    __shared__ float Ws[128 * F1];     // 16 KB
    int tid = threadIdx.x;
    for (int i = tid; i < 128 * F1; i += 256) Ws[i] = W1[i];
    __syncthreads();

    int warp = tid >> 5, lane = tid & 31;
    int base = blockIdx.x * 32 + warp * 4;

    float xr[4][4];
    bool valid[4];
#pragma unroll
    for (int r = 0; r < 4; r++) {
        int row = base + r;
        valid[r] = (row < n);
        const float* xp = x + (size_t)(valid[r] ? row : 0) * 128;
#pragma unroll
        for (int q = 0; q < 4; q++) xr[r][q] = xp[q * 32 + lane];
    }

    float acc[4] = {0.f, 0.f, 0.f, 0.f};
#pragma unroll
    for (int q = 0; q < 4; q++) {
#pragma unroll
        for (int kk = 0; kk < 32; kk++) {
            float wk = Ws[(q * 32 + kk) * F1 + lane];
#pragma unroll
            for (int r = 0; r < 4; r++) {
                float hv = __shfl_sync(0xffffffffu, xr[r][q], kk);
                acc[r] += hv * wk;
            }
        }
    }
#pragma unroll
    for (int r = 0; r < 4; r++)
        if (valid[r]) h1[(size_t)(base + r) * F1 + lane] = acc[r];
}

// ---------------- fused: agg1 = A_norm @ h1 ; h2 = lrelu(agg1+b1) @ W2 -----
// One warp per node; lane = feature (32). CSR edges read coalesced in
// 32-wide register chunks, broadcast via shfl.
__global__ void k_agg1_gemm2(const int* __restrict__ rowptr,
                             const int* __restrict__ cnt,
                             const int* __restrict__ src,
                             const float* __restrict__ wn,
                             const float* __restrict__ dinv,
                             const float* __restrict__ h1,
                             const float* __restrict__ b1,
                             const float* __restrict__ W2,
                             float* __restrict__ h2, int n) {
    __shared__ float W2s[F1 * F2];
    __shared__ float b1s[F1];
    int tid = threadIdx.x;
    for (int i = tid; i < F1 * F2; i += 256) W2s[i] = W2[i];
    if (tid < F1) b1s[tid] = b1[tid];
    __syncthreads();

    int node = (blockIdx.x * 256 + tid) >> 5;
    int lane = tid & 31;
    if (node >= n) return;

    float d = dinv[node];
    float acc = h1[(size_t)node * F1 + lane] * d * d;   // self-loop

    int beg = rowptr[node];
    int m   = cnt[node];
    int e   = 0;
    while (e < m) {
        int chunk = min(32, m - e);
        int   sreg = 0; float wreg = 0.f;
        if (lane < chunk) {
            sreg = src[beg + e + lane];
            wreg = wn [beg + e + lane];
        }
        for (int j = 0; j < chunk; j++) {
            int   s  = __shfl_sync(0xffffffffu, sreg, j);
            float ww = __shfl_sync(0xffffffffu, wreg, j);
            acc += h1[(size_t)s * F1 + lane] * ww;
        }
        e += chunk;
    }

    // layer-2 transform on the aggregated row
    float v = lrelu(acc + b1s[lane]);
    float o = 0.f;
    int f = lane & 15;
#pragma unroll
    for (int k = 0; k < F1; k++) {
        float hk = __shfl_sync(0xffffffffu, v, k);
        o += hk * W2s[k * F2 + f];
    }
    if (lane < F2) h2[(size_t)node * F2 + lane] = o;
}

// ---------------- fused: agg2 = A_norm @ h2 ; out = lrelu(agg2+b2)@Wfc+bfc -
// One warp per node; lanes = 16 features x 2 edge-parallel halves.
__global__ void k_agg2_final(const int* __restrict__ rowptr,
                             const int* __restrict__ cnt,
                             const int* __restrict__ src,
                             const float* __restrict__ wn,
                             const float* __restrict__ dinv,
                             const float* __restrict__ h2,
                             const float* __restrict__ b2,
                             const float* __restrict__ Wfc,
                             const float* __restrict__ bfc,
                             float* __restrict__ out, int n) {
    __shared__ float b2s[F2], wfs[F2];
    int tid = threadIdx.x;
    if (tid < F2) { b2s[tid] = b2[tid]; wfs[tid] = Wfc[tid]; }
    __syncthreads();

    int node = (blockIdx.x * 256 + tid) >> 5;
    int lane = tid & 31;
    if (node >= n) return;

    int f    = lane & 15;
    int half = lane >> 4;

    float acc = 0.f;
    if (half == 0) {
        float d = dinv[node];
        acc = h2[(size_t)node * F2 + f] * d * d;        // self-loop
    }

    int beg = rowptr[node];
    int m   = cnt[node];
    int e   = 0;
    while (e < m) {
        int chunk = min(32, m - e);
        int   sreg = 0; float wreg = 0.f;
        if (lane < chunk) {
            sreg = src[beg + e + lane];
            wreg = wn [beg + e + lane];
        }
        for (int j = 0; j < chunk; j += 2) {
            int jj = j + half;
            int   s  = __shfl_sync(0xffffffffu, sreg, jj & 31);
            float ww = __shfl_sync(0xffffffffu, wreg, jj & 31);
            if (jj < chunk) acc += h2[(size_t)s * F2 + f] * ww;
        }
        e += chunk;
    }

    acc += __shfl_xor_sync(0xffffffffu, acc, 16);       // merge halves

    float v = lrelu(acc + b2s[f]) * wfs[f];
    v += __shfl_xor_sync(0xffffffffu, v, 8);
    v += __shfl_xor_sync(0xffffffffu, v, 4);
    v += __shfl_xor_sync(0xffffffffu, v, 2);
    v += __shfl_xor_sync(0xffffffffu, v, 1);
    if (lane == 0) out[node] = v + bfc[0];
}

// ---------------- launcher --------------------------------------------------
extern "C" void kernel_launch(void* const* d_in, const int* in_sizes, int n_in,
                              void* d_out, int out_size) {
    const float* x   = (const float*)d_in[0];
    const int*   ei  = (const int*)d_in[1];
    const float* w   = (const float*)d_in[2];
    const float* W1  = (const float*)d_in[3];
    const float* b1  = (const float*)d_in[4];
    const float* W2  = (const float*)d_in[5];
    const float* b2  = (const float*)d_in[6];
    const float* Wfc = (const float*)d_in[7];
    const float* bfc = (const float*)d_in[8];
    float*       out = (float*)d_out;

    int n = in_sizes[0] / 128;   // 100000
    int e = in_sizes[2];         // 3200000

    float *deg, *dinv, *h1, *h2, *wn;
    int *cnt, *rowptr, *cursor, *bsum, *src;
    cudaGetSymbolAddress((void**)&deg,    g_deg);
    cudaGetSymbolAddress((void**)&dinv,   g_dinv);
    cudaGetSymbolAddress((void**)&cnt,    g_cnt);
    cudaGetSymbolAddress((void**)&rowptr, g_rowptr);
    cudaGetSymbolAddress((void**)&cursor, g_cursor);
    cudaGetSymbolAddress((void**)&bsum,   g_bsum);
    cudaGetSymbolAddress((void**)&src,    g_src);
    cudaGetSymbolAddress((void**)&wn,     g_wn);
    cudaGetSymbolAddress((void**)&h1,     g_h1);
    cudaGetSymbolAddress((void**)&h2,     g_h2);

    int nb = (n + SCAN_BLK - 1) / SCAN_BLK;   // 98 <= 128

    // normalization + CSR build
    k_init <<<(n + 255) / 256, 256>>>(deg, cnt, n);
    k_count<<<(e + 255) / 256, 256>>>(ei, w, deg, cnt, e, n);
    k_dinv <<<(n + 255) / 256, 256>>>(deg, dinv, n);
    k_scan1<<<nb, SCAN_BLK>>>(cnt, rowptr, bsum, n);
    k_scan2<<<1, 128>>>(bsum, nb);
    k_scan3<<<(n + 255) / 256, 256>>>(rowptr, cursor, bsum, n);
    k_fill <<<(e + 255) / 256, 256>>>(ei, w, dinv, cursor, src, wn, e, n);

    // layer 1 transform (overlappable with CSR build ordering-wise, but
    // stream-serialized here; it only needs x/W1)
    k_gemm1<<<(n + 31) / 32, 256>>>(x, W1, h1, n);

    // fused aggregation + layer-2 transform
    k_agg1_gemm2<<<(n * 32 + 255) / 256, 256>>>(rowptr, cnt, src, wn, dinv,
                                                h1, b1, W2, h2, n);

    // fused aggregation + output head
    k_agg2_final<<<(n * 32 + 255) / 256, 256>>>(rowptr, cnt, src, wn, dinv,
                                                h2, b2, Wfc, bfc, out, n);
}

// round 5
// speedup vs baseline: 2.4569x; 1.1016x over previous
#include <cuda_runtime.h>

// GCN_61701500174370: 2-layer GCN, N=100000 nodes, E=3200000 edges,
// features 128 -> 32 -> 16 -> 1, PyG gcn_norm with self-loops.
//
// Strategy: CSR by target node (built once per call, fused int2 edge records
// carrying {src, normalized weight}), deterministic warp-per-node gather
// reductions with ILP-4 pipelined gathers. Layer-1 aggregation fused with
// the layer-2 transform; layer-2 aggregation fused with the output head.
//
// Inputs (metadata order):
//  0: x        float32 [N,128]
//  1: edge_idx int32   [2,E]   row=ei[0:E], col=ei[E:2E]
//  2: edge_w   float32 [E]
//  3: W1 [128,32]  4: b1 [32]  5: W2 [32,16]  6: b2 [16]  7: Wfc [16,1]  8: bfc [1]
// Output: float32 [N,1]

#define GCN_N 100000
#define GCN_E 3200000
#define F1 32
#define F2 16
#define SCAN_BLK 1024

// ---------------- scratch (device globals; pointers fetched host-side) -----
__device__ float g_deg   [GCN_N];
__device__ float g_dinv  [GCN_N];
__device__ int   g_cnt   [GCN_N];
__device__ int   g_rowptr[GCN_N];
__device__ int   g_cursor[GCN_N];
__device__ int   g_bsum  [128];
__device__ int2  g_edge  [GCN_E];       // {src, __float_as_int(wn)}
__device__ float g_h1    [GCN_N * F1];
__device__ float g_h2    [GCN_N * F2];

static __device__ __forceinline__ float lrelu(float v) {
    return v > 0.0f ? v : 0.01f * v;
}

// ---------------- init: deg=1 (self-loop), cnt=0 ---------------------------
__global__ void k_init(float* __restrict__ deg, int* __restrict__ cnt, int n) {
    int i = blockIdx.x * blockDim.x + threadIdx.x;
    if (i < n) { deg[i] = 1.0f; cnt[i] = 0; }
}

// ---------------- weighted degree + edge count histogram -------------------
__global__ void k_count(const int* __restrict__ ei, const float* __restrict__ w,
                        float* __restrict__ deg, int* __restrict__ cnt,
                        int e_cnt, int n) {
    int e = blockIdx.x * blockDim.x + threadIdx.x;
    if (e < e_cnt) {
        int c = ei[e_cnt + e];
        if ((unsigned)c < (unsigned)n) {
            atomicAdd(deg + c, w[e]);
            atomicAdd(cnt + c, 1);
        }
    }
}

__global__ void k_dinv(const float* __restrict__ deg,
                       float* __restrict__ dinv, int n) {
    int i = blockIdx.x * blockDim.x + threadIdx.x;
    if (i < n) dinv[i] = rsqrtf(deg[i]);
}

// ---------------- exclusive scan of cnt -> rowptr (3 phases) ---------------
__global__ void k_scan1(const int* __restrict__ cnt, int* __restrict__ rowptr,
                        int* __restrict__ bsum, int n) {
    __shared__ int s[SCAN_BLK];
    int tid = threadIdx.x;
    int i = blockIdx.x * SCAN_BLK + tid;
    int own = (i < n) ? cnt[i] : 0;
    s[tid] = own;
    __syncthreads();
#pragma unroll
    for (int off = 1; off < SCAN_BLK; off <<= 1) {
        int t = (tid >= off) ? s[tid - off] : 0;
        __syncthreads();
        s[tid] += t;
        __syncthreads();
    }
    if (i < n) rowptr[i] = s[tid] - own;          // exclusive
    if (tid == SCAN_BLK - 1) bsum[blockIdx.x] = s[tid];  // block total
}

__global__ void k_scan2(int* __restrict__ bsum, int nb) {
    __shared__ int s[128];
    int tid = threadIdx.x;
    int own = (tid < nb) ? bsum[tid] : 0;
    s[tid] = own;
    __syncthreads();
#pragma unroll
    for (int off = 1; off < 128; off <<= 1) {
        int t = (tid >= off) ? s[tid - off] : 0;
        __syncthreads();
        s[tid] += t;
        __syncthreads();
    }
    if (tid < nb) bsum[tid] = s[tid] - own;       // exclusive block offsets
}

__global__ void k_scan3(int* __restrict__ rowptr, int* __restrict__ cursor,
                        const int* __restrict__ bsum, int n) {
    int i = blockIdx.x * blockDim.x + threadIdx.x;
    if (i < n) {
        int v = rowptr[i] + bsum[i / SCAN_BLK];
        rowptr[i] = v;
        cursor[i] = v;
    }
}

// ---------------- CSR fill: fused {src, normalized weight} records ---------
__global__ void k_fill(const int* __restrict__ ei, const float* __restrict__ w,
                       const float* __restrict__ dinv,
                       int* __restrict__ cursor,
                       int2* __restrict__ edge,
                       int e_cnt, int n) {
    int e = blockIdx.x * blockDim.x + threadIdx.x;
    if (e < e_cnt) {
        int r = ei[e];
        int c = ei[e_cnt + e];
        if ((unsigned)r < (unsigned)n && (unsigned)c < (unsigned)n) {
            int pos = atomicAdd(cursor + c, 1);
            float wnv = dinv[r] * w[e] * dinv[c];
            edge[pos] = make_int2(r, __float_as_int(wnv));
        }
    }
}

// ---------------- layer-1 transform: h1 = x @ W1 ---------------------------
// 8 warps/block, 8 rows/warp; W1 staged in shared, x via register shfl.
__global__ void k_gemm1(const float* __restrict__ x,
                        const float* __restrict__ W1,
                        float* __restrict__ h1, int n) {
    __shared__ float Ws[128 * F1];     // 16 KB
    int tid = threadIdx.x;
    for (int i = tid; i < 128 * F1; i += 256) Ws[i] = W1[i];
    __syncthreads();

    int warp = tid >> 5, lane = tid & 31;
    int base = blockIdx.x * 64 + warp * 8;

    const float* xp[8];
#pragma unroll
    for (int r = 0; r < 8; r++) {
        int row = base + r; if (row >= n) row = n - 1;
        xp[r] = x + (size_t)row * 128;
    }

    float acc[8] = {0.f, 0.f, 0.f, 0.f, 0.f, 0.f, 0.f, 0.f};
    for (int q = 0; q < 4; q++) {            // rolled: keeps body in I$
        float xq[8];
#pragma unroll
        for (int r = 0; r < 8; r++) xq[r] = xp[r][q * 32 + lane];
#pragma unroll
        for (int kk = 0; kk < 32; kk++) {
            float wk = Ws[(q * 32 + kk) * F1 + lane];
#pragma unroll
            for (int r = 0; r < 8; r++)
                acc[r] += __shfl_sync(0xffffffffu, xq[r], kk) * wk;
        }
    }
#pragma unroll
    for (int r = 0; r < 8; r++)
        if (base + r < n) h1[(size_t)(base + r) * F1 + lane] = acc[r];
}

// ---------------- fused: agg1 = A_norm @ h1 ; h2 = lrelu(agg1+b1) @ W2 -----
// One warp per node; lane = feature. ILP-4 gather pipeline, zero-padded tail.
__global__ void k_agg1_gemm2(const int* __restrict__ rowptr,
                             const int* __restrict__ cnt,
                             const int2* __restrict__ edge,
                             const float* __restrict__ dinv,
                             const float* __restrict__ h1,
                             const float* __restrict__ b1,
                             const float* __restrict__ W2,
                             float* __restrict__ h2, int n) {
    __shared__ float W2s[F1 * F2];
    __shared__ float b1s[F1];
    int tid = threadIdx.x;
    for (int i = tid; i < F1 * F2; i += 256) W2s[i] = W2[i];
    if (tid < F1) b1s[tid] = b1[tid];
    __syncthreads();

    int node = (blockIdx.x * 256 + tid) >> 5;
    int lane = tid & 31;
    if (node >= n) return;

    float d = dinv[node];
    float acc = h1[(size_t)node * F1 + lane] * d * d;   // self-loop

    int beg = rowptr[node];
    int m   = cnt[node];
    for (int e = 0; e < m; e += 32) {
        int take = m - e; if (take > 32) take = 32;
        int2 ed = (lane < take) ? edge[beg + e + lane] : make_int2(0, 0);
        float wv = __int_as_float(ed.y);
        int jmax = (take + 3) & ~3;
        for (int j = 0; j < jmax; j += 4) {
            int   s0 = __shfl_sync(0xffffffffu, ed.x, j);
            int   s1 = __shfl_sync(0xffffffffu, ed.x, j + 1);
            int   s2 = __shfl_sync(0xffffffffu, ed.x, j + 2);
            int   s3 = __shfl_sync(0xffffffffu, ed.x, j + 3);
            float w0 = __shfl_sync(0xffffffffu, wv, j);
            float w1 = __shfl_sync(0xffffffffu, wv, j + 1);
            float w2 = __shfl_sync(0xffffffffu, wv, j + 2);
            float w3 = __shfl_sync(0xffffffffu, wv, j + 3);
            float v0 = h1[(size_t)(s0 * F1) + lane];
            float v1 = h1[(size_t)(s1 * F1) + lane];
            float v2 = h1[(size_t)(s2 * F1) + lane];
            float v3 = h1[(size_t)(s3 * F1) + lane];
            acc += v0 * w0;
            acc += v1 * w1;
            acc += v2 * w2;
            acc += v3 * w3;
        }
    }

    // layer-2 transform on the aggregated row
    float v = lrelu(acc + b1s[lane]);
    float o = 0.f;
    int f = lane & 15;
#pragma unroll
    for (int k = 0; k < F1; k++) {
        float hk = __shfl_sync(0xffffffffu, v, k);
        o += hk * W2s[k * F2 + f];
    }
    if (lane < F2) h2[(size_t)node * F2 + lane] = o;
}

// ---------------- fused: agg2 = A_norm @ h2 ; out = lrelu(agg2+b2)@Wfc+bfc -
// One warp per node; 16 feature lanes x 2 edge-parallel halves, ILP-4 each.
__global__ void k_agg2_final(const int* __restrict__ rowptr,
                             const int* __restrict__ cnt,
                             const int2* __restrict__ edge,
                             const float* __restrict__ dinv,
                             const float* __restrict__ h2,
                             const float* __restrict__ b2,
                             const float* __restrict__ Wfc,
                             const float* __restrict__ bfc,
                             float* __restrict__ out, int n) {
    __shared__ float b2s[F2], wfs[F2];
    int tid = threadIdx.x;
    if (tid < F2) { b2s[tid] = b2[tid]; wfs[tid] = Wfc[tid]; }
    __syncthreads();

    int node = (blockIdx.x * 256 + tid) >> 5;
    int lane = tid & 31;
    if (node >= n) return;

    int f    = lane & 15;
    int half = lane >> 4;

    float acc = 0.f;
    if (half == 0) {
        float d = dinv[node];
        acc = h2[(size_t)node * F2 + f] * d * d;        // self-loop
    }

    int beg = rowptr[node];
    int m   = cnt[node];
    for (int e = 0; e < m; e += 32) {
        int take = m - e; if (take > 32) take = 32;
        int2 ed = (lane < take) ? edge[beg + e + lane] : make_int2(0, 0);
        float wv = __int_as_float(ed.y);
        int jmax = (take + 7) & ~7;
        for (int j = 0; j < jmax; j += 8) {
            int   s0 = __shfl_sync(0xffffffffu, ed.x, j + 0 + half);
            int   s1 = __shfl_sync(0xffffffffu, ed.x, j + 2 + half);
            int   s2 = __shfl_sync(0xffffffffu, ed.x, j + 4 + half);
            int   s3 = __shfl_sync(0xffffffffu, ed.x, j + 6 + half);
            float w0 = __shfl_sync(0xffffffffu, wv, j + 0 + half);
            float w1 = __shfl_sync(0xffffffffu, wv, j + 2 + half);
            float w2 = __shfl_sync(0xffffffffu, wv, j + 4 + half);
            float w3 = __shfl_sync(0xffffffffu, wv, j + 6 + half);
            float v0 = h2[(size_t)(s0 * F2) + f];
            float v1 = h2[(size_t)(s1 * F2) + f];
            float v2 = h2[(size_t)(s2 * F2) + f];
            float v3 = h2[(size_t)(s3 * F2) + f];
            acc += v0 * w0;
            acc += v1 * w1;
            acc += v2 * w2;
            acc += v3 * w3;
        }
    }

    acc += __shfl_xor_sync(0xffffffffu, acc, 16);       // merge halves

    float v = lrelu(acc + b2s[f]) * wfs[f];
    v += __shfl_xor_sync(0xffffffffu, v, 8);
    v += __shfl_xor_sync(0xffffffffu, v, 4);
    v += __shfl_xor_sync(0xffffffffu, v, 2);
    v += __shfl_xor_sync(0xffffffffu, v, 1);
    if (lane == 0) out[node] = v + bfc[0];
}

// ---------------- launcher --------------------------------------------------
extern "C" void kernel_launch(void* const* d_in, const int* in_sizes, int n_in,
                              void* d_out, int out_size) {
    const float* x   = (const float*)d_in[0];
    const int*   ei  = (const int*)d_in[1];
    const float* w   = (const float*)d_in[2];
    const float* W1  = (const float*)d_in[3];
    const float* b1  = (const float*)d_in[4];
    const float* W2  = (const float*)d_in[5];
    const float* b2  = (const float*)d_in[6];
    const float* Wfc = (const float*)d_in[7];
    const float* bfc = (const float*)d_in[8];
    float*       out = (float*)d_out;

    int n = in_sizes[0] / 128;   // 100000
    int e = in_sizes[2];         // 3200000

    float *deg, *dinv, *h1, *h2;
    int *cnt, *rowptr, *cursor, *bsum;
    int2 *edge;
    cudaGetSymbolAddress((void**)&deg,    g_deg);
    cudaGetSymbolAddress((void**)&dinv,   g_dinv);
    cudaGetSymbolAddress((void**)&cnt,    g_cnt);
    cudaGetSymbolAddress((void**)&rowptr, g_rowptr);
    cudaGetSymbolAddress((void**)&cursor, g_cursor);
    cudaGetSymbolAddress((void**)&bsum,   g_bsum);
    cudaGetSymbolAddress((void**)&edge,   g_edge);
    cudaGetSymbolAddress((void**)&h1,     g_h1);
    cudaGetSymbolAddress((void**)&h2,     g_h2);

    int nb = (n + SCAN_BLK - 1) / SCAN_BLK;   // 98 <= 128

    // normalization + CSR build
    k_init <<<(n + 255) / 256, 256>>>(deg, cnt, n);
    k_count<<<(e + 255) / 256, 256>>>(ei, w, deg, cnt, e, n);
    k_dinv <<<(n + 255) / 256, 256>>>(deg, dinv, n);
    k_scan1<<<nb, SCAN_BLK>>>(cnt, rowptr, bsum, n);
    k_scan2<<<1, 128>>>(bsum, nb);
    k_scan3<<<(n + 255) / 256, 256>>>(rowptr, cursor, bsum, n);
    k_fill <<<(e + 255) / 256, 256>>>(ei, w, dinv, cursor, edge, e, n);

    // layer 1 transform
    k_gemm1<<<(n + 63) / 64, 256>>>(x, W1, h1, n);

    // fused aggregation + layer-2 transform
    k_agg1_gemm2<<<(n * 32 + 255) / 256, 256>>>(rowptr, cnt, edge, dinv,
                                                h1, b1, W2, h2, n);

    // fused aggregation + output head
    k_agg2_final<<<(n * 32 + 255) / 256, 256>>>(rowptr, cnt, edge, dinv,
                                                h2, b2, Wfc, bfc, out, n);
}

// round 6
// speedup vs baseline: 2.5964x; 1.0568x over previous
#include <cuda_runtime.h>

// GCN_61701500174370: 2-layer GCN, N=100000 nodes, E=3200000 edges,
// features 128 -> 32 -> 16 -> 1, PyG gcn_norm with self-loops.
//
// Strategy: CSR by target node, raw edge weights in fused int2 records,
// degrees computed deterministically from CSR segments (no float atomics),
// normalization factored as agg[c] = dinv[c]*(sum w*(dinv[r]h[r]) + dinv[c]h[c])
// so each layer's features are stored pre-scaled by dinv. gemm1 overlapped
// with the CSR build via stream fork-join (capture-safe event pattern).
//
// Inputs (metadata order):
//  0: x        float32 [N,128]
//  1: edge_idx int32   [2,E]   row=ei[0:E], col=ei[E:2E]
//  2: edge_w   float32 [E]
//  3: W1 [128,32]  4: b1 [32]  5: W2 [32,16]  6: b2 [16]  7: Wfc [16,1]  8: bfc [1]
// Output: float32 [N,1]

#define GCN_N 100000
#define GCN_E 3200000
#define F1 32
#define F2 16
#define SCAN_BLK 1024

// ---------------- scratch (device globals; pointers fetched host-side) -----
__device__ float g_dinv  [GCN_N];
__device__ int   g_cnt   [GCN_N];
__device__ int   g_rowptr[GCN_N];
__device__ int   g_cursor[GCN_N];
__device__ int   g_bsum  [128];
__device__ int2  g_edge  [GCN_E];       // {src, __float_as_int(raw w)}
__device__ float g_h1    [GCN_N * F1];  // after k_scale: dinv[i]*h1[i]
__device__ float g_h2    [GCN_N * F2];  // stored pre-scaled: dinv[i]*h2[i]

static __device__ __forceinline__ float lrelu(float v) {
    return v > 0.0f ? v : 0.01f * v;
}

// ---------------- init: cnt=0 ----------------------------------------------
__global__ void k_init(int* __restrict__ cnt, int n) {
    int i = blockIdx.x * blockDim.x + threadIdx.x;
    if (i < n) cnt[i] = 0;
}

// ---------------- edge count histogram (int atomics only) ------------------
__global__ void k_count(const int* __restrict__ ei, int* __restrict__ cnt,
                        int e_cnt, int n) {
    int e = blockIdx.x * blockDim.x + threadIdx.x;
    if (e < e_cnt) {
        int c = ei[e_cnt + e];
        if ((unsigned)c < (unsigned)n) atomicAdd(cnt + c, 1);
    }
}

// ---------------- exclusive scan of cnt -> rowptr (3 phases) ---------------
__global__ void k_scan1(const int* __restrict__ cnt, int* __restrict__ rowptr,
                        int* __restrict__ bsum, int n) {
    __shared__ int s[SCAN_BLK];
    int tid = threadIdx.x;
    int i = blockIdx.x * SCAN_BLK + tid;
    int own = (i < n) ? cnt[i] : 0;
    s[tid] = own;
    __syncthreads();
#pragma unroll
    for (int off = 1; off < SCAN_BLK; off <<= 1) {
        int t = (tid >= off) ? s[tid - off] : 0;
        __syncthreads();
        s[tid] += t;
        __syncthreads();
    }
    if (i < n) rowptr[i] = s[tid] - own;          // exclusive
    if (tid == SCAN_BLK - 1) bsum[blockIdx.x] = s[tid];  // block total
}

__global__ void k_scan2(int* __restrict__ bsum, int nb) {
    __shared__ int s[128];
    int tid = threadIdx.x;
    int own = (tid < nb) ? bsum[tid] : 0;
    s[tid] = own;
    __syncthreads();
#pragma unroll
    for (int off = 1; off < 128; off <<= 1) {
        int t = (tid >= off) ? s[tid - off] : 0;
        __syncthreads();
        s[tid] += t;
        __syncthreads();
    }
    if (tid < nb) bsum[tid] = s[tid] - own;       // exclusive block offsets
}

__global__ void k_scan3(int* __restrict__ rowptr, int* __restrict__ cursor,
                        const int* __restrict__ bsum, int n) {
    int i = blockIdx.x * blockDim.x + threadIdx.x;
    if (i < n) {
        int v = rowptr[i] + bsum[i / SCAN_BLK];
        rowptr[i] = v;
        cursor[i] = v;
    }
}

// ---------------- CSR fill: {src, raw weight} (no dinv gathers) ------------
__global__ void k_fill(const int* __restrict__ ei, const float* __restrict__ w,
                       int* __restrict__ cursor, int2* __restrict__ edge,
                       int e_cnt, int n) {
    int e = blockIdx.x * blockDim.x + threadIdx.x;
    if (e < e_cnt) {
        int r = ei[e];
        int c = ei[e_cnt + e];
        if ((unsigned)r < (unsigned)n && (unsigned)c < (unsigned)n) {
            int pos = atomicAdd(cursor + c, 1);
            edge[pos] = make_int2(r, __float_as_int(w[e]));
        }
    }
}

// ---------------- deg = 1 + segment sum of w; dinv = rsqrt(deg) ------------
__global__ void k_degsum(const int* __restrict__ rowptr,
                         const int* __restrict__ cnt,
                         const int2* __restrict__ edge,
                         float* __restrict__ dinv, int n) {
    int node = (blockIdx.x * 256 + threadIdx.x) >> 5;
    int lane = threadIdx.x & 31;
    if (node >= n) return;
    int beg = rowptr[node], m = cnt[node];
    float s = 0.f;
    for (int e = lane; e < m; e += 32) s += __int_as_float(edge[beg + e].y);
    s += __shfl_xor_sync(0xffffffffu, s, 16);
    s += __shfl_xor_sync(0xffffffffu, s, 8);
    s += __shfl_xor_sync(0xffffffffu, s, 4);
    s += __shfl_xor_sync(0xffffffffu, s, 2);
    s += __shfl_xor_sync(0xffffffffu, s, 1);
    if (lane == 0) dinv[node] = rsqrtf(1.0f + s);
}

// ---------------- layer-1 transform: h1 = x @ W1 (runs on side stream) -----
__global__ void k_gemm1(const float* __restrict__ x,
                        const float* __restrict__ W1,
                        float* __restrict__ h1, int n) {
    __shared__ float Ws[128 * F1];     // 16 KB
    int tid = threadIdx.x;
    for (int i = tid; i < 128 * F1; i += 256) Ws[i] = W1[i];
    __syncthreads();

    int warp = tid >> 5, lane = tid & 31;
    int base = blockIdx.x * 64 + warp * 8;

    const float* xp[8];
#pragma unroll
    for (int r = 0; r < 8; r++) {
        int row = base + r; if (row >= n) row = n - 1;
        xp[r] = x + (size_t)row * 128;
    }

    float acc[8] = {0.f, 0.f, 0.f, 0.f, 0.f, 0.f, 0.f, 0.f};
    for (int q = 0; q < 4; q++) {            // rolled: keeps body in I$
        float xq[8];
#pragma unroll
        for (int r = 0; r < 8; r++) xq[r] = xp[r][q * 32 + lane];
#pragma unroll
        for (int kk = 0; kk < 32; kk++) {
            float wk = Ws[(q * 32 + kk) * F1 + lane];
#pragma unroll
            for (int r = 0; r < 8; r++)
                acc[r] += __shfl_sync(0xffffffffu, xq[r], kk) * wk;
        }
    }
#pragma unroll
    for (int r = 0; r < 8; r++)
        if (base + r < n) h1[(size_t)(base + r) * F1 + lane] = acc[r];
}

// ---------------- prescale: h1 <- dinv[node] * h1 ---------------------------
__global__ void k_scale(float* __restrict__ h1, const float* __restrict__ dinv,
                        int n) {
    int idx = blockIdx.x * blockDim.x + threadIdx.x;
    if (idx < n * F1) h1[idx] *= dinv[idx >> 5];
}

// ---------------- fused: agg1 + layer-2 transform ---------------------------
// h1 is pre-scaled by dinv. agg = dinv[c]*(sum w*h1p[r] + h1p[c]).
// h2 stored pre-scaled: h2p[c] = dinv[c]*h2[c].
__global__ void k_agg1_gemm2(const int* __restrict__ rowptr,
                             const int* __restrict__ cnt,
                             const int2* __restrict__ edge,
                             const float* __restrict__ dinv,
                             const float* __restrict__ h1,
                             const float* __restrict__ b1,
                             const float* __restrict__ W2,
                             float* __restrict__ h2, int n) {
    __shared__ float W2s[F1 * F2];
    __shared__ float b1s[F1];
    int tid = threadIdx.x;
    for (int i = tid; i < F1 * F2; i += 256) W2s[i] = W2[i];
    if (tid < F1) b1s[tid] = b1[tid];
    __syncthreads();

    int node = (blockIdx.x * 256 + tid) >> 5;
    int lane = tid & 31;
    if (node >= n) return;

    float acc = h1[(size_t)node * F1 + lane];   // self-loop term (pre-scaled)

    int beg = rowptr[node];
    int m   = cnt[node];
    for (int e = 0; e < m; e += 32) {
        int take = m - e; if (take > 32) take = 32;
        int2 ed = (lane < take) ? edge[beg + e + lane] : make_int2(0, 0);
        float wv = __int_as_float(ed.y);
        int jmax = (take + 3) & ~3;
        for (int j = 0; j < jmax; j += 4) {
            int   s0 = __shfl_sync(0xffffffffu, ed.x, j);
            int   s1 = __shfl_sync(0xffffffffu, ed.x, j + 1);
            int   s2 = __shfl_sync(0xffffffffu, ed.x, j + 2);
            int   s3 = __shfl_sync(0xffffffffu, ed.x, j + 3);
            float w0 = __shfl_sync(0xffffffffu, wv, j);
            float w1 = __shfl_sync(0xffffffffu, wv, j + 1);
            float w2 = __shfl_sync(0xffffffffu, wv, j + 2);
            float w3 = __shfl_sync(0xffffffffu, wv, j + 3);
            float v0 = h1[(size_t)(s0 * F1) + lane];
            float v1 = h1[(size_t)(s1 * F1) + lane];
            float v2 = h1[(size_t)(s2 * F1) + lane];
            float v3 = h1[(size_t)(s3 * F1) + lane];
            acc += v0 * w0;
            acc += v1 * w1;
            acc += v2 * w2;
            acc += v3 * w3;
        }
    }

    float d = dinv[node];
    float v = lrelu(d * acc + b1s[lane]);       // layer-1 activation
    float o = 0.f;
    int f = lane & 15;
#pragma unroll
    for (int k = 0; k < F1; k++) {
        float hk = __shfl_sync(0xffffffffu, v, k);
        o += hk * W2s[k * F2 + f];
    }
    if (lane < F2) h2[(size_t)node * F2 + lane] = d * o;   // pre-scaled
}

// ---------------- fused: agg2 + output head ---------------------------------
__global__ void k_agg2_final(const int* __restrict__ rowptr,
                             const int* __restrict__ cnt,
                             const int2* __restrict__ edge,
                             const float* __restrict__ dinv,
                             const float* __restrict__ h2,
                             const float* __restrict__ b2,
                             const float* __restrict__ Wfc,
                             const float* __restrict__ bfc,
                             float* __restrict__ out, int n) {
    __shared__ float b2s[F2], wfs[F2];
    int tid = threadIdx.x;
    if (tid < F2) { b2s[tid] = b2[tid]; wfs[tid] = Wfc[tid]; }
    __syncthreads();

    int node = (blockIdx.x * 256 + tid) >> 5;
    int lane = tid & 31;
    if (node >= n) return;

    int f    = lane & 15;
    int half = lane >> 4;

    float acc = (half == 0) ? h2[(size_t)node * F2 + f] : 0.f;  // self-loop

    int beg = rowptr[node];
    int m   = cnt[node];
    for (int e = 0; e < m; e += 32) {
        int take = m - e; if (take > 32) take = 32;
        int2 ed = (lane < take) ? edge[beg + e + lane] : make_int2(0, 0);
        float wv = __int_as_float(ed.y);
        int jmax = (take + 7) & ~7;
        for (int j = 0; j < jmax; j += 8) {
            int   s0 = __shfl_sync(0xffffffffu, ed.x, j + 0 + half);
            int   s1 = __shfl_sync(0xffffffffu, ed.x, j + 2 + half);
            int   s2 = __shfl_sync(0xffffffffu, ed.x, j + 4 + half);
            int   s3 = __shfl_sync(0xffffffffu, ed.x, j + 6 + half);
            float w0 = __shfl_sync(0xffffffffu, wv, j + 0 + half);
            float w1 = __shfl_sync(0xffffffffu, wv, j + 2 + half);
            float w2 = __shfl_sync(0xffffffffu, wv, j + 4 + half);
            float w3 = __shfl_sync(0xffffffffu, wv, j + 6 + half);
            float v0 = h2[(size_t)(s0 * F2) + f];
            float v1 = h2[(size_t)(s1 * F2) + f];
            float v2 = h2[(size_t)(s2 * F2) + f];
            float v3 = h2[(size_t)(s3 * F2) + f];
            acc += v0 * w0;
            acc += v1 * w1;
            acc += v2 * w2;
            acc += v3 * w3;
        }
    }

    acc += __shfl_xor_sync(0xffffffffu, acc, 16);       // merge halves

    float v = lrelu(dinv[node] * acc + b2s[f]) * wfs[f];
    v += __shfl_xor_sync(0xffffffffu, v, 8);
    v += __shfl_xor_sync(0xffffffffu, v, 4);
    v += __shfl_xor_sync(0xffffffffu, v, 2);
    v += __shfl_xor_sync(0xffffffffu, v, 1);
    if (lane == 0) out[node] = v + bfc[0];
}

// ---------------- launcher --------------------------------------------------
extern "C" void kernel_launch(void* const* d_in, const int* in_sizes, int n_in,
                              void* d_out, int out_size) {
    const float* x   = (const float*)d_in[0];
    const int*   ei  = (const int*)d_in[1];
    const float* w   = (const float*)d_in[2];
    const float* W1  = (const float*)d_in[3];
    const float* b1  = (const float*)d_in[4];
    const float* W2  = (const float*)d_in[5];
    const float* b2  = (const float*)d_in[6];
    const float* Wfc = (const float*)d_in[7];
    const float* bfc = (const float*)d_in[8];
    float*       out = (float*)d_out;

    int n = in_sizes[0] / 128;   // 100000
    int e = in_sizes[2];         // 3200000

    float *dinv, *h1, *h2;
    int *cnt, *rowptr, *cursor, *bsum;
    int2 *edge;
    cudaGetSymbolAddress((void**)&dinv,   g_dinv);
    cudaGetSymbolAddress((void**)&cnt,    g_cnt);
    cudaGetSymbolAddress((void**)&rowptr, g_rowptr);
    cudaGetSymbolAddress((void**)&cursor, g_cursor);
    cudaGetSymbolAddress((void**)&bsum,   g_bsum);
    cudaGetSymbolAddress((void**)&edge,   g_edge);
    cudaGetSymbolAddress((void**)&h1,     g_h1);
    cudaGetSymbolAddress((void**)&h2,     g_h2);

    int nb = (n + SCAN_BLK - 1) / SCAN_BLK;   // 98 <= 128

    // fork: gemm1 (independent of graph structure) on side stream
    cudaStream_t sB;
    cudaEvent_t evFork, evJoin;
    cudaStreamCreateWithFlags(&sB, cudaStreamNonBlocking);
    cudaEventCreateWithFlags(&evFork, cudaEventDisableTiming);
    cudaEventCreateWithFlags(&evJoin, cudaEventDisableTiming);

    cudaEventRecord(evFork, 0);
    cudaStreamWaitEvent(sB, evFork, 0);
    k_gemm1<<<(n + 63) / 64, 256, 0, sB>>>(x, W1, h1, n);
    cudaEventRecord(evJoin, sB);

    // CSR build chain on main stream
    k_init  <<<(n + 255) / 256, 256>>>(cnt, n);
    k_count <<<(e + 255) / 256, 256>>>(ei, cnt, e, n);
    k_scan1 <<<nb, SCAN_BLK>>>(cnt, rowptr, bsum, n);
    k_scan2 <<<1, 128>>>(bsum, nb);
    k_scan3 <<<(n + 255) / 256, 256>>>(rowptr, cursor, bsum, n);
    k_fill  <<<(e + 255) / 256, 256>>>(ei, w, cursor, edge, e, n);
    k_degsum<<<(n * 32 + 255) / 256, 256>>>(rowptr, cnt, edge, dinv, n);

    // join gemm1, then prescale h1 by dinv
    cudaStreamWaitEvent(0, evJoin, 0);
    k_scale<<<(n * F1 + 255) / 256, 256>>>(h1, dinv, n);

    // fused aggregation + layer-2 transform
    k_agg1_gemm2<<<(n * 32 + 255) / 256, 256>>>(rowptr, cnt, edge, dinv,
                                                h1, b1, W2, h2, n);

    // fused aggregation + output head
    k_agg2_final<<<(n * 32 + 255) / 256, 256>>>(rowptr, cnt, edge, dinv,
                                                h2, b2, Wfc, bfc, out, n);
}

// round 7
// speedup vs baseline: 2.6263x; 1.0115x over previous
#include <cuda_runtime.h>
#include <cuda_fp16.h>

// GCN_61701500174370: 2-layer GCN, N=100000 nodes, E=3200000 edges,
// features 128 -> 32 -> 16 -> 1, PyG gcn_norm with self-loops.
//
// CSR by target node (int2 {src, raw w} records), degrees from CSR segment
// sums (no float atomics), normalization factored so features are stored
// pre-scaled by dinv. Gathered feature arrays (h1, h2) stored as fp16
// (fp32 accumulation) to halve L2 gather traffic. gemm1 overlapped with the
// CSR build via stream fork-join.
//
// Inputs (metadata order):
//  0: x        float32 [N,128]
//  1: edge_idx int32   [2,E]   row=ei[0:E], col=ei[E:2E]
//  2: edge_w   float32 [E]
//  3: W1 [128,32]  4: b1 [32]  5: W2 [32,16]  6: b2 [16]  7: Wfc [16,1]  8: bfc [1]
// Output: float32 [N,1]

#define GCN_N 100000
#define GCN_E 3200000
#define F1 32
#define F2 16
#define SCAN_BLK 1024

// ---------------- scratch (device globals; pointers fetched host-side) -----
__device__ float  g_dinv  [GCN_N];
__device__ int    g_cnt   [GCN_N];
__device__ int    g_rowptr[GCN_N];
__device__ int    g_cursor[GCN_N];
__device__ int    g_bsum  [128];
__device__ int2   g_edge  [GCN_E];       // {src, __float_as_int(raw w)}
__device__ float  g_h1f   [GCN_N * F1];  // gemm1 output (fp32)
__device__ __half g_h1h   [GCN_N * F1];  // dinv-scaled h1 (fp16, gathered)
__device__ __half g_h2h   [GCN_N * F2];  // dinv-scaled h2 (fp16, gathered)

static __device__ __forceinline__ float lrelu(float v) {
    return v > 0.0f ? v : 0.01f * v;
}

// ---------------- edge count histogram (4 edges/thread, int4 loads) --------
__global__ void k_count(const int* __restrict__ ei, int* __restrict__ cnt,
                        int e_cnt, int n) {
    int t = blockIdx.x * blockDim.x + threadIdx.x;
    int base = t * 4;
    if (base + 3 < e_cnt) {
        int4 c4 = *(const int4*)(ei + e_cnt + base);
        if ((unsigned)c4.x < (unsigned)n) atomicAdd(cnt + c4.x, 1);
        if ((unsigned)c4.y < (unsigned)n) atomicAdd(cnt + c4.y, 1);
        if ((unsigned)c4.z < (unsigned)n) atomicAdd(cnt + c4.z, 1);
        if ((unsigned)c4.w < (unsigned)n) atomicAdd(cnt + c4.w, 1);
    } else {
        for (int e = base; e < e_cnt; e++) {
            int c = ei[e_cnt + e];
            if ((unsigned)c < (unsigned)n) atomicAdd(cnt + c, 1);
        }
    }
}

// ---------------- exclusive scan of cnt -> rowptr (3 phases) ---------------
__global__ void k_scan1(const int* __restrict__ cnt, int* __restrict__ rowptr,
                        int* __restrict__ bsum, int n) {
    __shared__ int s[SCAN_BLK];
    int tid = threadIdx.x;
    int i = blockIdx.x * SCAN_BLK + tid;
    int own = (i < n) ? cnt[i] : 0;
    s[tid] = own;
    __syncthreads();
#pragma unroll
    for (int off = 1; off < SCAN_BLK; off <<= 1) {
        int t = (tid >= off) ? s[tid - off] : 0;
        __syncthreads();
        s[tid] += t;
        __syncthreads();
    }
    if (i < n) rowptr[i] = s[tid] - own;          // exclusive
    if (tid == SCAN_BLK - 1) bsum[blockIdx.x] = s[tid];  // block total
}

__global__ void k_scan2(int* __restrict__ bsum, int nb) {
    __shared__ int s[128];
    int tid = threadIdx.x;
    int own = (tid < nb) ? bsum[tid] : 0;
    s[tid] = own;
    __syncthreads();
#pragma unroll
    for (int off = 1; off < 128; off <<= 1) {
        int t = (tid >= off) ? s[tid - off] : 0;
        __syncthreads();
        s[tid] += t;
        __syncthreads();
    }
    if (tid < nb) bsum[tid] = s[tid] - own;       // exclusive block offsets
}

__global__ void k_scan3(int* __restrict__ rowptr, int* __restrict__ cursor,
                        const int* __restrict__ bsum, int n) {
    int i = blockIdx.x * blockDim.x + threadIdx.x;
    if (i < n) {
        int v = rowptr[i] + bsum[i / SCAN_BLK];
        rowptr[i] = v;
        cursor[i] = v;
    }
}

// ---------------- CSR fill (4 edges/thread, vectorized streams) ------------
__global__ void k_fill(const int* __restrict__ ei, const float* __restrict__ w,
                       int* __restrict__ cursor, int2* __restrict__ edge,
                       int e_cnt, int n) {
    int t = blockIdx.x * blockDim.x + threadIdx.x;
    int base = t * 4;
    if (base + 3 < e_cnt) {
        int4   r4 = *(const int4*)(ei + base);
        int4   c4 = *(const int4*)(ei + e_cnt + base);
        float4 w4 = *(const float4*)(w + base);
        if ((unsigned)r4.x < (unsigned)n && (unsigned)c4.x < (unsigned)n) {
            int pos = atomicAdd(cursor + c4.x, 1);
            edge[pos] = make_int2(r4.x, __float_as_int(w4.x));
        }
        if ((unsigned)r4.y < (unsigned)n && (unsigned)c4.y < (unsigned)n) {
            int pos = atomicAdd(cursor + c4.y, 1);
            edge[pos] = make_int2(r4.y, __float_as_int(w4.y));
        }
        if ((unsigned)r4.z < (unsigned)n && (unsigned)c4.z < (unsigned)n) {
            int pos = atomicAdd(cursor + c4.z, 1);
            edge[pos] = make_int2(r4.z, __float_as_int(w4.z));
        }
        if ((unsigned)r4.w < (unsigned)n && (unsigned)c4.w < (unsigned)n) {
            int pos = atomicAdd(cursor + c4.w, 1);
            edge[pos] = make_int2(r4.w, __float_as_int(w4.w));
        }
    } else {
        for (int e = base; e < e_cnt; e++) {
            int r = ei[e], c = ei[e_cnt + e];
            if ((unsigned)r < (unsigned)n && (unsigned)c < (unsigned)n) {
                int pos = atomicAdd(cursor + c, 1);
                edge[pos] = make_int2(r, __float_as_int(w[e]));
            }
        }
    }
}

// ---------------- layer-1 transform: h1 = x @ W1 (side stream) -------------
__global__ void k_gemm1(const float* __restrict__ x,
                        const float* __restrict__ W1,
                        float* __restrict__ h1, int n) {
    __shared__ float Ws[128 * F1];     // 16 KB
    int tid = threadIdx.x;
    for (int i = tid; i < 128 * F1; i += 256) Ws[i] = W1[i];
    __syncthreads();

    int warp = tid >> 5, lane = tid & 31;
    int base = blockIdx.x * 64 + warp * 8;

    const float* xp[8];
#pragma unroll
    for (int r = 0; r < 8; r++) {
        int row = base + r; if (row >= n) row = n - 1;
        xp[r] = x + (size_t)row * 128;
    }

    float acc[8] = {0.f, 0.f, 0.f, 0.f, 0.f, 0.f, 0.f, 0.f};
    for (int q = 0; q < 4; q++) {            // rolled: keeps body in I$
        float xq[8];
#pragma unroll
        for (int r = 0; r < 8; r++) xq[r] = xp[r][q * 32 + lane];
#pragma unroll
        for (int kk = 0; kk < 32; kk++) {
            float wk = Ws[(q * 32 + kk) * F1 + lane];
#pragma unroll
            for (int r = 0; r < 8; r++)
                acc[r] += __shfl_sync(0xffffffffu, xq[r], kk) * wk;
        }
    }
#pragma unroll
    for (int r = 0; r < 8; r++)
        if (base + r < n) h1[(size_t)(base + r) * F1 + lane] = acc[r];
}

// ---------------- fused: deg from CSR, dinv, fp16 prescale of h1 -----------
// Warp per node: segment-sum raw weights -> dinv; then emit dinv*h1 as fp16.
__global__ void k_degscale(const int* __restrict__ rowptr,
                           const int* __restrict__ cnt,
                           const int2* __restrict__ edge,
                           float* __restrict__ dinv,
                           const float* __restrict__ h1f,
                           __half* __restrict__ h1h, int n) {
    int node = (blockIdx.x * 256 + threadIdx.x) >> 5;
    int lane = threadIdx.x & 31;
    if (node >= n) return;
    int beg = rowptr[node], m = cnt[node];
    float s = 0.f;
    for (int e = lane; e < m; e += 32) s += __int_as_float(edge[beg + e].y);
    s += __shfl_xor_sync(0xffffffffu, s, 16);
    s += __shfl_xor_sync(0xffffffffu, s, 8);
    s += __shfl_xor_sync(0xffffffffu, s, 4);
    s += __shfl_xor_sync(0xffffffffu, s, 2);
    s += __shfl_xor_sync(0xffffffffu, s, 1);
    float d = rsqrtf(1.0f + s);                 // deg = 1 + sum(w)
    if (lane == 0) dinv[node] = d;
    h1h[(size_t)node * F1 + lane] =
        __float2half(h1f[(size_t)node * F1 + lane] * d);
}

// ---------------- fused: agg1 + layer-2 transform ---------------------------
// agg = dinv[c]*(sum w*h1p[r] + h1p[c]); fp16 gathers, fp32 accumulation.
__global__ void k_agg1_gemm2(const int* __restrict__ rowptr,
                             const int* __restrict__ cnt,
                             const int2* __restrict__ edge,
                             const float* __restrict__ dinv,
                             const __half* __restrict__ h1h,
                             const float* __restrict__ b1,
                             const float* __restrict__ W2,
                             __half* __restrict__ h2h, int n) {
    __shared__ float W2s[F1 * F2];
    __shared__ float b1s[F1];
    int tid = threadIdx.x;
    for (int i = tid; i < F1 * F2; i += 256) W2s[i] = W2[i];
    if (tid < F1) b1s[tid] = b1[tid];
    __syncthreads();

    int node = (blockIdx.x * 256 + tid) >> 5;
    int lane = tid & 31;
    if (node >= n) return;

    float acc = __half2float(h1h[(size_t)node * F1 + lane]);  // self-loop

    int beg = rowptr[node];
    int m   = cnt[node];
    for (int e = 0; e < m; e += 32) {
        int take = m - e; if (take > 32) take = 32;
        int2 ed = (lane < take) ? edge[beg + e + lane] : make_int2(0, 0);
        float wv = __int_as_float(ed.y);
        int jmax = (take + 3) & ~3;
        for (int j = 0; j < jmax; j += 4) {
            int   s0 = __shfl_sync(0xffffffffu, ed.x, j);
            int   s1 = __shfl_sync(0xffffffffu, ed.x, j + 1);
            int   s2 = __shfl_sync(0xffffffffu, ed.x, j + 2);
            int   s3 = __shfl_sync(0xffffffffu, ed.x, j + 3);
            float w0 = __shfl_sync(0xffffffffu, wv, j);
            float w1 = __shfl_sync(0xffffffffu, wv, j + 1);
            float w2 = __shfl_sync(0xffffffffu, wv, j + 2);
            float w3 = __shfl_sync(0xffffffffu, wv, j + 3);
            float v0 = __half2float(h1h[(size_t)(s0 * F1) + lane]);
            float v1 = __half2float(h1h[(size_t)(s1 * F1) + lane]);
            float v2 = __half2float(h1h[(size_t)(s2 * F1) + lane]);
            float v3 = __half2float(h1h[(size_t)(s3 * F1) + lane]);
            acc += v0 * w0;
            acc += v1 * w1;
            acc += v2 * w2;
            acc += v3 * w3;
        }
    }

    float d = dinv[node];
    float v = lrelu(d * acc + b1s[lane]);       // layer-1 activation
    float o = 0.f;
    int f = lane & 15;
#pragma unroll
    for (int k = 0; k < F1; k++) {
        float hk = __shfl_sync(0xffffffffu, v, k);
        o += hk * W2s[k * F2 + f];
    }
    if (lane < F2) h2h[(size_t)node * F2 + lane] = __float2half(d * o);
}

// ---------------- fused: agg2 + output head ---------------------------------
__global__ void k_agg2_final(const int* __restrict__ rowptr,
                             const int* __restrict__ cnt,
                             const int2* __restrict__ edge,
                             const float* __restrict__ dinv,
                             const __half* __restrict__ h2h,
                             const float* __restrict__ b2,
                             const float* __restrict__ Wfc,
                             const float* __restrict__ bfc,
                             float* __restrict__ out, int n) {
    __shared__ float b2s[F2], wfs[F2];
    int tid = threadIdx.x;
    if (tid < F2) { b2s[tid] = b2[tid]; wfs[tid] = Wfc[tid]; }
    __syncthreads();

    int node = (blockIdx.x * 256 + tid) >> 5;
    int lane = tid & 31;
    if (node >= n) return;

    int f    = lane & 15;
    int half = lane >> 4;

    float acc = (half == 0) ? __half2float(h2h[(size_t)node * F2 + f]) : 0.f;

    int beg = rowptr[node];
    int m   = cnt[node];
    for (int e = 0; e < m; e += 32) {
        int take = m - e; if (take > 32) take = 32;
        int2 ed = (lane < take) ? edge[beg + e + lane] : make_int2(0, 0);
        float wv = __int_as_float(ed.y);
        int jmax = (take + 7) & ~7;
        for (int j = 0; j < jmax; j += 8) {
            int   s0 = __shfl_sync(0xffffffffu, ed.x, j + 0 + half);
            int   s1 = __shfl_sync(0xffffffffu, ed.x, j + 2 + half);
            int   s2 = __shfl_sync(0xffffffffu, ed.x, j + 4 + half);
            int   s3 = __shfl_sync(0xffffffffu, ed.x, j + 6 + half);
            float w0 = __shfl_sync(0xffffffffu, wv, j + 0 + half);
            float w1 = __shfl_sync(0xffffffffu, wv, j + 2 + half);
            float w2 = __shfl_sync(0xffffffffu, wv, j + 4 + half);
            float w3 = __shfl_sync(0xffffffffu, wv, j + 6 + half);
            float v0 = __half2float(h2h[(size_t)(s0 * F2) + f]);
            float v1 = __half2float(h2h[(size_t)(s1 * F2) + f]);
            float v2 = __half2float(h2h[(size_t)(s2 * F2) + f]);
            float v3 = __half2float(h2h[(size_t)(s3 * F2) + f]);
            acc += v0 * w0;
            acc += v1 * w1;
            acc += v2 * w2;
            acc += v3 * w3;
        }
    }

    acc += __shfl_xor_sync(0xffffffffu, acc, 16);       // merge halves

    float v = lrelu(dinv[node] * acc + b2s[f]) * wfs[f];
    v += __shfl_xor_sync(0xffffffffu, v, 8);
    v += __shfl_xor_sync(0xffffffffu, v, 4);
    v += __shfl_xor_sync(0xffffffffu, v, 2);
    v += __shfl_xor_sync(0xffffffffu, v, 1);
    if (lane == 0) out[node] = v + bfc[0];
}

// ---------------- launcher --------------------------------------------------
extern "C" void kernel_launch(void* const* d_in, const int* in_sizes, int n_in,
                              void* d_out, int out_size) {
    const float* x   = (const float*)d_in[0];
    const int*   ei  = (const int*)d_in[1];
    const float* w   = (const float*)d_in[2];
    const float* W1  = (const float*)d_in[3];
    const float* b1  = (const float*)d_in[4];
    const float* W2  = (const float*)d_in[5];
    const float* b2  = (const float*)d_in[6];
    const float* Wfc = (const float*)d_in[7];
    const float* bfc = (const float*)d_in[8];
    float*       out = (float*)d_out;

    int n = in_sizes[0] / 128;   // 100000
    int e = in_sizes[2];         // 3200000

    float *dinv, *h1f;
    __half *h1h, *h2h;
    int *cnt, *rowptr, *cursor, *bsum;
    int2 *edge;
    cudaGetSymbolAddress((void**)&dinv,   g_dinv);
    cudaGetSymbolAddress((void**)&cnt,    g_cnt);
    cudaGetSymbolAddress((void**)&rowptr, g_rowptr);
    cudaGetSymbolAddress((void**)&cursor, g_cursor);
    cudaGetSymbolAddress((void**)&bsum,   g_bsum);
    cudaGetSymbolAddress((void**)&edge,   g_edge);
    cudaGetSymbolAddress((void**)&h1f,    g_h1f);
    cudaGetSymbolAddress((void**)&h1h,    g_h1h);
    cudaGetSymbolAddress((void**)&h2h,    g_h2h);

    int nb = (n + SCAN_BLK - 1) / SCAN_BLK;   // 98 <= 128

    // fork: gemm1 (independent of graph structure) on side stream
    cudaStream_t sB;
    cudaEvent_t evFork, evJoin;
    cudaStreamCreateWithFlags(&sB, cudaStreamNonBlocking);
    cudaEventCreateWithFlags(&evFork, cudaEventDisableTiming);
    cudaEventCreateWithFlags(&evJoin, cudaEventDisableTiming);

    cudaEventRecord(evFork, 0);
    cudaStreamWaitEvent(sB, evFork, 0);
    k_gemm1<<<(n + 63) / 64, 256, 0, sB>>>(x, W1, h1f, n);
    cudaEventRecord(evJoin, sB);

    // CSR build chain on main stream
    cudaMemsetAsync(cnt, 0, (size_t)n * sizeof(int), 0);
    k_count<<<(e / 4 + 255) / 256, 256>>>(ei, cnt, e, n);
    k_scan1<<<nb, SCAN_BLK>>>(cnt, rowptr, bsum, n);
    k_scan2<<<1, 128>>>(bsum, nb);
    k_scan3<<<(n + 255) / 256, 256>>>(rowptr, cursor, bsum, n);
    k_fill <<<(e / 4 + 255) / 256, 256>>>(ei, w, cursor, edge, e, n);

    // join gemm1; degrees + dinv + fp16 prescale in one pass
    cudaStreamWaitEvent(0, evJoin, 0);
    k_degscale<<<(n * 32 + 255) / 256, 256>>>(rowptr, cnt, edge, dinv,
                                              h1f, h1h, n);

    // fused aggregation + layer-2 transform
    k_agg1_gemm2<<<(n * 32 + 255) / 256, 256>>>(rowptr, cnt, edge, dinv,
                                                h1h, b1, W2, h2h, n);

    // fused aggregation + output head
    k_agg2_final<<<(n * 32 + 255) / 256, 256>>>(rowptr, cnt, edge, dinv,
                                                h2h, b2, Wfc, bfc, out, n);
}